// round 7
// baseline (speedup 1.0000x reference)
#include <cuda_runtime.h>
#include <cstdint>

#define NBLK 1184   // 148 SMs * 8 CTAs
#define NTHR 256

__device__ float g_psum[NBLK];
__device__ int   g_pcnt[NBLK];
__device__ int   g_ticket;   // zero-initialized; reset to 0 by last block each run

// Accumulate log2-domain; scale by -ln2 once at the end.
__device__ __forceinline__ void bce_elem(float p, int t, float& s, int& c) {
    float q = (t == 1) ? p : (1.0f - p);     // argument select: 1 FADD + 1 FSEL
    float l = __log2f(q);                    // single MUFU.LG2
    bool  keep = ((unsigned)t) < 2u;
    s += keep ? l : 0.0f;                    // FSEL + FADD
    c += keep ? 1 : 0;                       // ISETP + IADD
}

__global__ __launch_bounds__(NTHR) void bce_fused_kernel(
    const float* __restrict__ prob,
    const int* __restrict__ tgt,
    int n16,         // number of 16-element groups
    float* __restrict__ out)
{
    const float4* p4 = reinterpret_cast<const float4*>(prob);
    const int4*   t4 = reinterpret_cast<const int4*>(tgt);

    float s = 0.0f;  // sum of log2(q) over kept elements
    int   c = 0;

    int stride = gridDim.x * blockDim.x;
    for (int i = blockIdx.x * blockDim.x + threadIdx.x; i < n16; i += stride) {
        // Front-batch all 8 vector loads for MLP
        float4 pa = __ldcs(&p4[4 * i]);
        float4 pb = __ldcs(&p4[4 * i + 1]);
        float4 pc = __ldcs(&p4[4 * i + 2]);
        float4 pd = __ldcs(&p4[4 * i + 3]);
        int4   ta = __ldcs(&t4[4 * i]);
        int4   tb = __ldcs(&t4[4 * i + 1]);
        int4   tc = __ldcs(&t4[4 * i + 2]);
        int4   td = __ldcs(&t4[4 * i + 3]);
        bce_elem(pa.x, ta.x, s, c);
        bce_elem(pa.y, ta.y, s, c);
        bce_elem(pa.z, ta.z, s, c);
        bce_elem(pa.w, ta.w, s, c);
        bce_elem(pb.x, tb.x, s, c);
        bce_elem(pb.y, tb.y, s, c);
        bce_elem(pb.z, tb.z, s, c);
        bce_elem(pb.w, tb.w, s, c);
        bce_elem(pc.x, tc.x, s, c);
        bce_elem(pc.y, tc.y, s, c);
        bce_elem(pc.z, tc.z, s, c);
        bce_elem(pc.w, tc.w, s, c);
        bce_elem(pd.x, td.x, s, c);
        bce_elem(pd.y, td.y, s, c);
        bce_elem(pd.z, td.z, s, c);
        bce_elem(pd.w, td.w, s, c);
    }

    // Convert to natural-log domain, negated: sum(-ln q) = -ln2 * sum(log2 q)
    s *= -0.69314718055994530942f;

    // Block reduction
    __shared__ float ss[NTHR];
    __shared__ int   sc[NTHR];
    __shared__ bool  is_last;
    int tid = threadIdx.x;
    ss[tid] = s;
    sc[tid] = c;
    __syncthreads();
    #pragma unroll
    for (int off = NTHR / 2; off >= 32; off >>= 1) {
        if (tid < off) {
            ss[tid] += ss[tid + off];
            sc[tid] += sc[tid + off];
        }
        __syncthreads();
    }
    if (tid < 32) {
        float ws = ss[tid];
        int   wc = sc[tid];
        #pragma unroll
        for (int off = 16; off > 0; off >>= 1) {
            ws += __shfl_down_sync(0xFFFFFFFFu, ws, off);
            wc += __shfl_down_sync(0xFFFFFFFFu, wc, off);
        }
        if (tid == 0) {
            g_psum[blockIdx.x] = ws;
            g_pcnt[blockIdx.x] = wc;
            __threadfence();
            int ticket = atomicAdd(&g_ticket, 1);
            is_last = (ticket == gridDim.x - 1);
        }
    }
    __syncthreads();

    // Last block to finish performs the final reduction (deterministic order)
    if (is_last) {
        float fs = 0.0f;
        int   fc = 0;
        for (int i = tid; i < NBLK; i += NTHR) {
            fs += g_psum[i];
            fc += g_pcnt[i];
        }
        ss[tid] = fs;
        sc[tid] = fc;
        __syncthreads();
        #pragma unroll
        for (int off = NTHR / 2; off >= 32; off >>= 1) {
            if (tid < off) {
                ss[tid] += ss[tid + off];
                sc[tid] += sc[tid + off];
            }
            __syncthreads();
        }
        if (tid < 32) {
            float ws = ss[tid];
            int   wc = sc[tid];
            #pragma unroll
            for (int off = 16; off > 0; off >>= 1) {
                ws += __shfl_down_sync(0xFFFFFFFFu, ws, off);
                wc += __shfl_down_sync(0xFFFFFFFFu, wc, off);
            }
            if (tid == 0) {
                out[0] = ws / (float)wc;
                atomicExch(&g_ticket, 0);   // reset for next graph replay
            }
        }
    }
}

extern "C" void kernel_launch(void* const* d_in, const int* in_sizes, int n_in,
                              void* d_out, int out_size) {
    const float* prob = (const float*)d_in[0];
    const int*   tgt  = (const int*)d_in[1];
    float*       out  = (float*)d_out;

    int n   = in_sizes[0];   // 40,960,000 (divisible by 16)
    int n16 = n / 16;

    bce_fused_kernel<<<NBLK, NTHR>>>(prob, tgt, n16, out);
}

// round 8
// speedup vs baseline: 1.0387x; 1.0387x over previous
#include <cuda_runtime.h>
#include <cstdint>

#define NBLK 1184   // 148 SMs * 8 CTAs
#define NTHR 256

__device__ float g_psum[NBLK];
__device__ int   g_pcnt[NBLK];
__device__ int   g_ticket;   // zero-initialized; reset to 0 by last block each run

// Accumulate log2-domain; scale by -ln2 once at the end.
__device__ __forceinline__ void bce_elem(float p, int t, float& s, int& c) {
    float q = (t == 1) ? p : (1.0f - p);     // argument select
    float l = __log2f(q);                    // single MUFU.LG2
    bool  keep = ((unsigned)t) < 2u;
    s += keep ? l : 0.0f;
    c += keep ? 1 : 0;
}

__global__ __launch_bounds__(NTHR) void bce_fused_kernel(
    const float* __restrict__ prob,
    const int* __restrict__ tgt,
    int n4,          // number of 4-element groups
    float* __restrict__ out)
{
    const float4* p4 = reinterpret_cast<const float4*>(prob);
    const int4*   t4 = reinterpret_cast<const int4*>(tgt);

    float s = 0.0f;  // sum of log2(q) over kept elements
    int   c = 0;

    int stride = gridDim.x * blockDim.x;
    for (int i = blockIdx.x * blockDim.x + threadIdx.x; i < n4; i += stride) {
        float4 p = p4[i];
        int4   t = t4[i];
        bce_elem(p.x, t.x, s, c);
        bce_elem(p.y, t.y, s, c);
        bce_elem(p.z, t.z, s, c);
        bce_elem(p.w, t.w, s, c);
    }

    // Convert to natural-log domain, negated: sum(-ln q) = -ln2 * sum(log2 q)
    s *= -0.69314718055994530942f;

    // Block reduction
    __shared__ float ss[NTHR];
    __shared__ int   sc[NTHR];
    __shared__ bool  is_last;
    int tid = threadIdx.x;
    ss[tid] = s;
    sc[tid] = c;
    __syncthreads();
    #pragma unroll
    for (int off = NTHR / 2; off >= 32; off >>= 1) {
        if (tid < off) {
            ss[tid] += ss[tid + off];
            sc[tid] += sc[tid + off];
        }
        __syncthreads();
    }
    if (tid < 32) {
        float ws = ss[tid];
        int   wc = sc[tid];
        #pragma unroll
        for (int off = 16; off > 0; off >>= 1) {
            ws += __shfl_down_sync(0xFFFFFFFFu, ws, off);
            wc += __shfl_down_sync(0xFFFFFFFFu, wc, off);
        }
        if (tid == 0) {
            g_psum[blockIdx.x] = ws;
            g_pcnt[blockIdx.x] = wc;
            __threadfence();
            int ticket = atomicAdd(&g_ticket, 1);
            is_last = (ticket == gridDim.x - 1);
        }
    }
    __syncthreads();

    // Last block to finish performs the final reduction (deterministic order)
    if (is_last) {
        float fs = 0.0f;
        int   fc = 0;
        for (int i = tid; i < NBLK; i += NTHR) {
            fs += g_psum[i];
            fc += g_pcnt[i];
        }
        ss[tid] = fs;
        sc[tid] = fc;
        __syncthreads();
        #pragma unroll
        for (int off = NTHR / 2; off >= 32; off >>= 1) {
            if (tid < off) {
                ss[tid] += ss[tid + off];
                sc[tid] += sc[tid + off];
            }
            __syncthreads();
        }
        if (tid < 32) {
            float ws = ss[tid];
            int   wc = sc[tid];
            #pragma unroll
            for (int off = 16; off > 0; off >>= 1) {
                ws += __shfl_down_sync(0xFFFFFFFFu, ws, off);
                wc += __shfl_down_sync(0xFFFFFFFFu, wc, off);
            }
            if (tid == 0) {
                out[0] = ws / (float)wc;
                atomicExch(&g_ticket, 0);   // reset for next graph replay
            }
        }
    }
}

extern "C" void kernel_launch(void* const* d_in, const int* in_sizes, int n_in,
                              void* d_out, int out_size) {
    const float* prob = (const float*)d_in[0];
    const int*   tgt  = (const int*)d_in[1];
    float*       out  = (float*)d_out;

    int n  = in_sizes[0];   // 40,960,000 (divisible by 4)
    int n4 = n / 4;

    bce_fused_kernel<<<NBLK, NTHR>>>(prob, tgt, n4, out);
}

// round 10
// speedup vs baseline: 1.0773x; 1.0372x over previous
#include <cuda_runtime.h>
#include <cstdint>

#define NBLK 1184   // 148 SMs * 8 CTAs
#define NTHR 256

__device__ float g_sum;     // zero-init; reset by last block each run
__device__ int   g_cnt;
__device__ int   g_ticket;

// Accumulate log2-domain; scale by -ln2 once at the end.
__device__ __forceinline__ void bce_elem(float p, int t, float& s, int& c) {
    float q = (t == 1) ? p : (1.0f - p);     // argument select
    float l = __log2f(q);                    // single MUFU.LG2
    bool  keep = ((unsigned)t) < 2u;
    s += keep ? l : 0.0f;
    c += keep ? 1 : 0;
}

__global__ __launch_bounds__(NTHR) void bce_fused_kernel(
    const float* __restrict__ prob,
    const int* __restrict__ tgt,
    int n4,          // number of 4-element groups
    float* __restrict__ out)
{
    const float4* p4 = reinterpret_cast<const float4*>(prob);
    const int4*   t4 = reinterpret_cast<const int4*>(tgt);

    float s = 0.0f;  // sum of log2(q) over kept elements
    int   c = 0;

    int stride = gridDim.x * blockDim.x;
    for (int i = blockIdx.x * blockDim.x + threadIdx.x; i < n4; i += stride) {
        float4 p = p4[i];
        int4   t = t4[i];
        bce_elem(p.x, t.x, s, c);
        bce_elem(p.y, t.y, s, c);
        bce_elem(p.z, t.z, s, c);
        bce_elem(p.w, t.w, s, c);
    }

    // Convert to natural-log domain, negated: sum(-ln q) = -ln2 * sum(log2 q)
    s *= -0.69314718055994530942f;

    // Block reduction
    __shared__ float ss[NTHR];
    __shared__ int   sc[NTHR];
    int tid = threadIdx.x;
    ss[tid] = s;
    sc[tid] = c;
    __syncthreads();
    #pragma unroll
    for (int off = NTHR / 2; off >= 32; off >>= 1) {
        if (tid < off) {
            ss[tid] += ss[tid + off];
            sc[tid] += sc[tid + off];
        }
        __syncthreads();
    }
    if (tid < 32) {
        float ws = ss[tid];
        int   wc = sc[tid];
        #pragma unroll
        for (int off = 16; off > 0; off >>= 1) {
            ws += __shfl_down_sync(0xFFFFFFFFu, ws, off);
            wc += __shfl_down_sync(0xFFFFFFFFu, wc, off);
        }
        if (tid == 0) {
            // Per-block contribution straight to global accumulators.
            atomicAdd(&g_sum, ws);
            atomicAdd(&g_cnt, wc);
            __threadfence();
            int ticket = atomicAdd(&g_ticket, 1);
            if (ticket == gridDim.x - 1) {
                // All 1183 prior blocks' atomics are globally visible
                // (their fence precedes their ticket increment).
                float fs = g_sum;
                int   fc = g_cnt;
                out[0] = fs / (float)fc;
                // Reset for the next graph replay (atomics: unambiguous vs
                // any interleaving at the replay boundary).
                atomicExch(&g_sum, 0.0f);
                atomicExch(&g_cnt, 0);
                atomicExch(&g_ticket, 0);
            }
        }
    }
}

extern "C" void kernel_launch(void* const* d_in, const int* in_sizes, int n_in,
                              void* d_out, int out_size) {
    const float* prob = (const float*)d_in[0];
    const int*   tgt  = (const int*)d_in[1];
    float*       out  = (float*)d_out;

    int n  = in_sizes[0];   // 40,960,000 (divisible by 4)
    int n4 = n / 4;

    bce_fused_kernel<<<NBLK, NTHR>>>(prob, tgt, n4, out);
}

// round 12
// speedup vs baseline: 1.0793x; 1.0018x over previous
#include <cuda_runtime.h>
#include <cstdint>

#define NBLK 592    // 148 SMs * 4 CTAs
#define NTHR 512

__device__ float g_sum;     // zero-init; reset by last block each run
__device__ int   g_cnt;
__device__ int   g_ticket;

// Accumulate log2-domain; scale by -ln2 once at the end.
__device__ __forceinline__ void bce_elem(float p, int t, float& s, int& c) {
    float q = (t == 1) ? p : (1.0f - p);     // argument select
    float l = __log2f(q);                    // single MUFU.LG2
    bool  keep = ((unsigned)t) < 2u;
    s += keep ? l : 0.0f;
    c += keep ? 1 : 0;
}

__global__ __launch_bounds__(NTHR) void bce_fused_kernel(
    const float* __restrict__ prob,
    const int* __restrict__ tgt,
    int n4,          // number of 4-element groups
    float* __restrict__ out)
{
    const float4* p4 = reinterpret_cast<const float4*>(prob);
    const int4*   t4 = reinterpret_cast<const int4*>(tgt);

    float s = 0.0f;  // sum of log2(q) over kept elements
    int   c = 0;

    int stride = gridDim.x * blockDim.x;
    for (int i = blockIdx.x * blockDim.x + threadIdx.x; i < n4; i += stride) {
        float4 p = p4[i];
        int4   t = t4[i];
        bce_elem(p.x, t.x, s, c);
        bce_elem(p.y, t.y, s, c);
        bce_elem(p.z, t.z, s, c);
        bce_elem(p.w, t.w, s, c);
    }

    // Convert to natural-log domain, negated: sum(-ln q) = -ln2 * sum(log2 q)
    s *= -0.69314718055994530942f;

    // Block reduction
    __shared__ float ss[NTHR];
    __shared__ int   sc[NTHR];
    int tid = threadIdx.x;
    ss[tid] = s;
    sc[tid] = c;
    __syncthreads();
    #pragma unroll
    for (int off = NTHR / 2; off >= 32; off >>= 1) {
        if (tid < off) {
            ss[tid] += ss[tid + off];
            sc[tid] += sc[tid + off];
        }
        __syncthreads();
    }
    if (tid < 32) {
        float ws = ss[tid];
        int   wc = sc[tid];
        #pragma unroll
        for (int off = 16; off > 0; off >>= 1) {
            ws += __shfl_down_sync(0xFFFFFFFFu, ws, off);
            wc += __shfl_down_sync(0xFFFFFFFFu, wc, off);
        }
        if (tid == 0) {
            // Per-block contribution straight to global accumulators.
            atomicAdd(&g_sum, ws);
            atomicAdd(&g_cnt, wc);
            __threadfence();
            int ticket = atomicAdd(&g_ticket, 1);
            if (ticket == gridDim.x - 1) {
                // All prior blocks' atomics are globally visible
                // (their fence precedes their ticket increment).
                float fs = g_sum;
                int   fc = g_cnt;
                out[0] = fs / (float)fc;
                // Reset for the next graph replay.
                atomicExch(&g_sum, 0.0f);
                atomicExch(&g_cnt, 0);
                atomicExch(&g_ticket, 0);
            }
        }
    }
}

extern "C" void kernel_launch(void* const* d_in, const int* in_sizes, int n_in,
                              void* d_out, int out_size) {
    const float* prob = (const float*)d_in[0];
    const int*   tgt  = (const int*)d_in[1];
    float*       out  = (float*)d_out;

    int n  = in_sizes[0];   // 40,960,000 (divisible by 4)
    int n4 = n / 4;

    bce_fused_kernel<<<NBLK, NTHR>>>(prob, tgt, n4, out);
}